// round 15
// baseline (speedup 1.0000x reference)
#include <cuda_runtime.h>
#include <cstdint>

// out[b,i,j] = x[b, i, i+j] if i+j < L else 0
// B=4, L=4096, LIMIT=256
#define MAXLEN 4096
#define LIMIT  256
#define BATCH  4

#define NROWS     (BATCH * MAXLEN)     // 16384
#define NSM       148
#define OCC       8
#define NBLOCKS   (NSM * OCC)          // 1184 persistent CTAs (one wave)
#define TPB       256                  // 8 warps; warp handles one row per trip
#define ROWSTRIDE (NBLOCKS * (TPB/32)) // 9472 rows per sweep
#define FULLM     0xFFFFFFFFu

// w1[lane] = src[lane+1], with src[32] supplied by nxt (same value all lanes)
__device__ __forceinline__ float4 shift_down1(float4 src, float4 nxt, int lane)
{
    float4 r;
    r.x = __shfl_down_sync(FULLM, src.x, 1);
    r.y = __shfl_down_sync(FULLM, src.y, 1);
    r.z = __shfl_down_sync(FULLM, src.z, 1);
    r.w = __shfl_down_sync(FULLM, src.w, 1);
    if (lane == 31) r = nxt;
    return r;
}

__device__ __forceinline__ void do_row(const float* __restrict__ x,
                                       float* __restrict__ out,
                                       int row, int lane)
{
    const int i   = row & (MAXLEN - 1);
    const int a   = i & 3;                   // misalignment, warp-uniform
    const int bc4 = i >> 2;                  // first aligned f4 block in row
    const int lim = MAXLEN - i;              // j < lim is valid
    const float4* __restrict__ xr =
        reinterpret_cast<const float4*>(x) + ((size_t)row << 10);
    float4* __restrict__ orow =
        reinterpret_cast<float4*>(out) + ((size_t)row << 6);

    // Each 16B block loaded exactly ONCE, L2-only (no reuse -> skip L1).
    const float4 A = __ldcg(xr + min(bc4 + lane,      1023));   // blocks 0..31
    const float4 B = __ldcg(xr + min(bc4 + 32 + lane, 1023));   // blocks 32..63
    const float4 C = __ldcg(xr + min(bc4 + 64,        1023));   // block 64 (bcast)

    const float4 B0x = { __shfl_sync(FULLM, B.x, 0), __shfl_sync(FULLM, B.y, 0),
                         __shfl_sync(FULLM, B.z, 0), __shfl_sync(FULLM, B.w, 0) };

    #pragma unroll
    for (int it = 0; it < 2; it++) {
        const int o = lane + it * 32;        // output f4 index (0..63)
        const float4 w0 = it ? B : A;
        const float4 w1 = it ? shift_down1(B, C,   lane)
                             : shift_down1(A, B0x, lane);

        float4 v;                            // funnel shift by a floats
        if      (a == 0) { v.x = w0.x; v.y = w0.y; v.z = w0.z; v.w = w0.w; }
        else if (a == 1) { v.x = w0.y; v.y = w0.z; v.z = w0.w; v.w = w1.x; }
        else if (a == 2) { v.x = w0.z; v.y = w0.w; v.z = w1.x; v.w = w1.y; }
        else             { v.x = w0.w; v.y = w1.x; v.z = w1.y; v.w = w1.z; }

        const int j0 = o << 2;
        if (j0 + 3 >= lim) {                 // rare tail rows only
            if (j0 + 0 >= lim) v.x = 0.0f;
            if (j0 + 1 >= lim) v.y = 0.0f;
            if (j0 + 2 >= lim) v.z = 0.0f;
            if (j0 + 3 >= lim) v.w = 0.0f;
        }
        orow[o] = v;
    }
}

__global__ __launch_bounds__(TPB, OCC)
void band_gather_kernel(const float* __restrict__ x, float* __restrict__ out)
{
    const int lane = threadIdx.x & 31;
    const int warp = blockIdx.x * (TPB / 32) + (threadIdx.x >> 5);

    do_row(x, out, warp, lane);              // rows 0..9471

    const int row2 = warp + ROWSTRIDE;       // rows 9472..16383
    if (row2 < NROWS)
        do_row(x, out, row2, lane);
}

extern "C" void kernel_launch(void* const* d_in, const int* in_sizes, int n_in,
                              void* d_out, int out_size)
{
    (void)in_sizes; (void)n_in; (void)out_size;
    const float* x = (const float*)d_in[0];
    float* out = (float*)d_out;
    band_gather_kernel<<<NBLOCKS, TPB>>>(x, out);
}

// round 16
// speedup vs baseline: 1.0294x; 1.0294x over previous
#include <cuda_runtime.h>
#include <cstdint>

// out[b,i,j] = x[b, i, i+j] if i+j < L else 0
// B=4, L=4096, LIMIT=256
//
// FINAL KERNEL (R8/R13 structure — measured best across 15 rounds):
//  - persistent single-wave grid: 1184 CTAs (148 SM x 8), warp-per-row,
//    second trip predicated (wave-transition cost eliminated, R7)
//  - every 16B source block loaded exactly ONCE via __ldcg (L1 bypass,
//    zero-reuse data); the +16B shifted neighbor is synthesized with
//    __shfl_down instead of a second load (halves load wavefronts, R8)
//  - warp-uniform funnel shift by (i & 3); coalesced plain STG.128
// Bound by compulsory mixed-stream memory traffic (~35.7 MB @ ~6.3 TB/s
// ~= 5.4us) plus fixed launch overhead (~2.2us).
#define MAXLEN 4096
#define LIMIT  256
#define BATCH  4

#define NROWS     (BATCH * MAXLEN)     // 16384
#define NSM       148
#define OCC       8
#define NBLOCKS   (NSM * OCC)          // 1184 persistent CTAs (one wave)
#define TPB       256                  // 8 warps; warp handles one row per trip
#define ROWSTRIDE (NBLOCKS * (TPB/32)) // 9472 rows per sweep
#define FULLM     0xFFFFFFFFu

// w1[lane] = src[lane+1], with src[32] supplied by nxt (same value all lanes)
__device__ __forceinline__ float4 shift_down1(float4 src, float4 nxt, int lane)
{
    float4 r;
    r.x = __shfl_down_sync(FULLM, src.x, 1);
    r.y = __shfl_down_sync(FULLM, src.y, 1);
    r.z = __shfl_down_sync(FULLM, src.z, 1);
    r.w = __shfl_down_sync(FULLM, src.w, 1);
    if (lane == 31) r = nxt;
    return r;
}

__device__ __forceinline__ void do_row(const float* __restrict__ x,
                                       float* __restrict__ out,
                                       int row, int lane)
{
    const int i   = row & (MAXLEN - 1);
    const int a   = i & 3;                   // misalignment, warp-uniform
    const int bc4 = i >> 2;                  // first aligned f4 block in row
    const int lim = MAXLEN - i;              // j < lim is valid
    const float4* __restrict__ xr =
        reinterpret_cast<const float4*>(x) + ((size_t)row << 10);
    float4* __restrict__ orow =
        reinterpret_cast<float4*>(out) + ((size_t)row << 6);

    // Each 16B block loaded exactly ONCE, L2-only (no reuse -> skip L1).
    const float4 A = __ldcg(xr + min(bc4 + lane,      1023));   // blocks 0..31
    const float4 B = __ldcg(xr + min(bc4 + 32 + lane, 1023));   // blocks 32..63
    const float4 C = __ldcg(xr + min(bc4 + 64,        1023));   // block 64 (bcast)

    const float4 B0x = { __shfl_sync(FULLM, B.x, 0), __shfl_sync(FULLM, B.y, 0),
                         __shfl_sync(FULLM, B.z, 0), __shfl_sync(FULLM, B.w, 0) };

    #pragma unroll
    for (int it = 0; it < 2; it++) {
        const int o = lane + it * 32;        // output f4 index (0..63)
        const float4 w0 = it ? B : A;
        const float4 w1 = it ? shift_down1(B, C,   lane)
                             : shift_down1(A, B0x, lane);

        float4 v;                            // funnel shift by a floats
        if      (a == 0) { v.x = w0.x; v.y = w0.y; v.z = w0.z; v.w = w0.w; }
        else if (a == 1) { v.x = w0.y; v.y = w0.z; v.z = w0.w; v.w = w1.x; }
        else if (a == 2) { v.x = w0.z; v.y = w0.w; v.z = w1.x; v.w = w1.y; }
        else             { v.x = w0.w; v.y = w1.x; v.z = w1.y; v.w = w1.z; }

        const int j0 = o << 2;
        if (j0 + 3 >= lim) {                 // rare tail rows only
            if (j0 + 0 >= lim) v.x = 0.0f;
            if (j0 + 1 >= lim) v.y = 0.0f;
            if (j0 + 2 >= lim) v.z = 0.0f;
            if (j0 + 3 >= lim) v.w = 0.0f;
        }
        orow[o] = v;
    }
}

__global__ __launch_bounds__(TPB, OCC)
void band_gather_kernel(const float* __restrict__ x, float* __restrict__ out)
{
    const int lane = threadIdx.x & 31;
    const int warp = blockIdx.x * (TPB / 32) + (threadIdx.x >> 5);

    do_row(x, out, warp, lane);              // rows 0..9471

    const int row2 = warp + ROWSTRIDE;       // rows 9472..16383
    if (row2 < NROWS)
        do_row(x, out, row2, lane);
}

extern "C" void kernel_launch(void* const* d_in, const int* in_sizes, int n_in,
                              void* d_out, int out_size)
{
    (void)in_sizes; (void)n_in; (void)out_size;
    const float* x = (const float*)d_in[0];
    float* out = (float*)d_out;
    band_gather_kernel<<<NBLOCKS, TPB>>>(x, out);
}

// round 17
// speedup vs baseline: 1.0332x; 1.0037x over previous
#include <cuda_runtime.h>
#include <cstdint>

// out[b,i,j] = x[b, i, i+j] if i+j < L else 0
// B=4, L=4096, LIMIT=256
//
// FINAL KERNEL (R8/R13/R16 structure — measured best across 16 rounds):
//  - persistent single-wave grid: 1184 CTAs (148 SM x 8), warp-per-row,
//    second trip predicated (wave-transition cost eliminated, R7)
//  - every 16B source block loaded exactly ONCE via __ldcg (L1 bypass,
//    zero-reuse data); the +16B shifted neighbor is synthesized with
//    __shfl_down instead of a second load (halves load wavefronts, R8)
//  - warp-uniform funnel shift by (i & 3); coalesced plain STG.128
// Bound by compulsory mixed-stream memory traffic (~35.7 MB @ ~6.3 TB/s
// ~= 5.4us) plus fixed launch/ramp overhead (~2.3us).
#define MAXLEN 4096
#define LIMIT  256
#define BATCH  4

#define NROWS     (BATCH * MAXLEN)     // 16384
#define NSM       148
#define OCC       8
#define NBLOCKS   (NSM * OCC)          // 1184 persistent CTAs (one wave)
#define TPB       256                  // 8 warps; warp handles one row per trip
#define ROWSTRIDE (NBLOCKS * (TPB/32)) // 9472 rows per sweep
#define FULLM     0xFFFFFFFFu

// w1[lane] = src[lane+1], with src[32] supplied by nxt (same value all lanes)
__device__ __forceinline__ float4 shift_down1(float4 src, float4 nxt, int lane)
{
    float4 r;
    r.x = __shfl_down_sync(FULLM, src.x, 1);
    r.y = __shfl_down_sync(FULLM, src.y, 1);
    r.z = __shfl_down_sync(FULLM, src.z, 1);
    r.w = __shfl_down_sync(FULLM, src.w, 1);
    if (lane == 31) r = nxt;
    return r;
}

__device__ __forceinline__ void do_row(const float* __restrict__ x,
                                       float* __restrict__ out,
                                       int row, int lane)
{
    const int i   = row & (MAXLEN - 1);
    const int a   = i & 3;                   // misalignment, warp-uniform
    const int bc4 = i >> 2;                  // first aligned f4 block in row
    const int lim = MAXLEN - i;              // j < lim is valid
    const float4* __restrict__ xr =
        reinterpret_cast<const float4*>(x) + ((size_t)row << 10);
    float4* __restrict__ orow =
        reinterpret_cast<float4*>(out) + ((size_t)row << 6);

    // Each 16B block loaded exactly ONCE, L2-only (no reuse -> skip L1).
    const float4 A = __ldcg(xr + min(bc4 + lane,      1023));   // blocks 0..31
    const float4 B = __ldcg(xr + min(bc4 + 32 + lane, 1023));   // blocks 32..63
    const float4 C = __ldcg(xr + min(bc4 + 64,        1023));   // block 64 (bcast)

    const float4 B0x = { __shfl_sync(FULLM, B.x, 0), __shfl_sync(FULLM, B.y, 0),
                         __shfl_sync(FULLM, B.z, 0), __shfl_sync(FULLM, B.w, 0) };

    #pragma unroll
    for (int it = 0; it < 2; it++) {
        const int o = lane + it * 32;        // output f4 index (0..63)
        const float4 w0 = it ? B : A;
        const float4 w1 = it ? shift_down1(B, C,   lane)
                             : shift_down1(A, B0x, lane);

        float4 v;                            // funnel shift by a floats
        if      (a == 0) { v.x = w0.x; v.y = w0.y; v.z = w0.z; v.w = w0.w; }
        else if (a == 1) { v.x = w0.y; v.y = w0.z; v.z = w0.w; v.w = w1.x; }
        else if (a == 2) { v.x = w0.z; v.y = w0.w; v.z = w1.x; v.w = w1.y; }
        else             { v.x = w0.w; v.y = w1.x; v.z = w1.y; v.w = w1.z; }

        const int j0 = o << 2;
        if (j0 + 3 >= lim) {                 // rare tail rows only
            if (j0 + 0 >= lim) v.x = 0.0f;
            if (j0 + 1 >= lim) v.y = 0.0f;
            if (j0 + 2 >= lim) v.z = 0.0f;
            if (j0 + 3 >= lim) v.w = 0.0f;
        }
        orow[o] = v;
    }
}

__global__ __launch_bounds__(TPB, OCC)
void band_gather_kernel(const float* __restrict__ x, float* __restrict__ out)
{
    const int lane = threadIdx.x & 31;
    const int warp = blockIdx.x * (TPB / 32) + (threadIdx.x >> 5);

    do_row(x, out, warp, lane);              // rows 0..9471

    const int row2 = warp + ROWSTRIDE;       // rows 9472..16383
    if (row2 < NROWS)
        do_row(x, out, row2, lane);
}

extern "C" void kernel_launch(void* const* d_in, const int* in_sizes, int n_in,
                              void* d_out, int out_size)
{
    (void)in_sizes; (void)n_in; (void)out_size;
    const float* x = (const float*)d_in[0];
    float* out = (float*)d_out;
    band_gather_kernel<<<NBLOCKS, TPB>>>(x, out);
}